// round 13
// baseline (speedup 1.0000x reference)
#include <cuda_runtime.h>
#include <cuda_fp16.h>
#include <cstdint>
#include <math.h>

// ---------------------------------------------------------------------------
// Problem constants
// ---------------------------------------------------------------------------
#define C_TOT   2048
#define HW2     196
#define O_REAL  48
#define MAXB    64
#define M_TILE  32
#define MTILES  392            // 12544 / 32
#define K_PER   1024           // per ks-half
#define KC      128
#define NCH_CTA 8              // chunks per ks-half
#define NCH_ALL 16
#define NSTEP   32             // k32 steps per ks-half

// W fp16 image: per chunk, 48 rows x 68 words (64 data + 4 pad)
#define ROWW    68
#define CHUNKW  (48 * ROWW)            // 3264 words
#define CHUNK_BYTES (CHUNKW * 4)       // 13056
#define CP_UNITS (CHUNK_BYTES / 16)    // 816

#define XST     49                     // epilogue smem row stride (conflict-free)
#define SMEM_BYTES (4 * CHUNK_BYTES)   // 52224 (2 streams x double buffer)

// Scratch
__device__ uint32_t g_wimg[(size_t)NCH_ALL * CHUNKW];        // 209 KB
__device__ float    g_csum[(size_t)MAXB * HW2 * 8];          // [m][8]
__device__ float    g_t2[(size_t)MAXB * HW2 * 8];            // [m][8]
__device__ float    g_t1s[(size_t)MAXB * 8];                 // atomicAdd acc
__device__ unsigned g_gmp_u[(size_t)MAXB * 32];              // atomicMax acc
__device__ int      g_bdone[MAXB];                           // per-b tickets

// ---------------------------------------------------------------------------
// helpers
// ---------------------------------------------------------------------------
__device__ __forceinline__ void hmma16816(float* c, const uint32_t* a,
                                          uint32_t b0, uint32_t b1) {
    asm volatile(
        "mma.sync.aligned.m16n8k16.row.col.f32.f16.f16.f32 "
        "{%0,%1,%2,%3}, {%4,%5,%6,%7}, {%8,%9}, {%0,%1,%2,%3};"
        : "+f"(c[0]), "+f"(c[1]), "+f"(c[2]), "+f"(c[3])
        : "r"(a[0]), "r"(a[1]), "r"(a[2]), "r"(a[3]), "r"(b0), "r"(b1));
}
__device__ __forceinline__ uint32_t h2pack(float e, float o) {
    uint32_t r;
    asm("cvt.rn.f16x2.f32 %0, %1, %2;" : "=r"(r) : "f"(o), "f"(e));
    return r;
}
__device__ __forceinline__ void cp_async16(uint32_t saddr, const void* gaddr) {
    asm volatile("cp.async.cg.shared.global [%0], [%1], 16;" :: "r"(saddr), "l"(gaddr));
}
__device__ __forceinline__ uint32_t smem_u32addr(const void* p) {
    uint32_t a;
    asm("{ .reg .u64 t; cvta.to.shared.u64 t, %1; cvt.u32.u64 %0, t; }" : "=r"(a) : "l"(p));
    return a;
}
__device__ __forceinline__ unsigned fenc(float f) {
    unsigned u = __float_as_uint(f);
    return (u & 0x80000000u) ? ~u : (u | 0x80000000u);
}
__device__ __forceinline__ float fdec(unsigned u) {
    return __uint_as_float((u & 0x80000000u) ? (u & 0x7FFFFFFFu) : ~u);
}
// number of 32-row tiles overlapping batch b's rows [196b, 196b+196)
__device__ __forceinline__ int tiles_of_b(int b) {
    return ((HW2 * b + HW2 - 1) >> 5) - ((HW2 * b) >> 5) + 1;
}

// ---------------------------------------------------------------------------
// Prep: W -> fp16 image (4 words/thread) + zero accumulators & tickets.
// ---------------------------------------------------------------------------
__global__ void __launch_bounds__(256) wsl_prep_kernel(
    const float* __restrict__ down_w,
    const float* __restrict__ fc_w)
{
    int q = blockIdx.x * 256 + threadIdx.x;

    if (q < MAXB * 32) g_gmp_u[q] = 0u;
    if (q < MAXB * 8)  g_t1s[q] = 0.f;
    if (q < MAXB)      g_bdone[q] = 0;

    if (q >= NCH_ALL * 48 * 16) return;
    int ci  = q / 768;
    int rem = q - ci * 768;
    int n   = rem >> 4;
    int qd  = rem & 15;
    int s   = qd >> 1;
    int bk  = s * 16 + 4 * (qd & 1);

    const float* wr;
    if (n < 32)      wr = down_w + (size_t)n * C_TOT;
    else if (n < 40) wr = fc_w + (size_t)(n - 32) * (2 * C_TOT);
    else             wr = fc_w + (size_t)(n - 40) * (2 * C_TOT) + C_TOT;

    const float* src = wr + ci * KC + bk;
    float4 f0 = *reinterpret_cast<const float4*>(src);
    float4 f1 = *reinterpret_cast<const float4*>(src + 8);

    uint4 v;
    v.x = h2pack(f0.x, f0.y);
    v.y = h2pack(f1.x, f1.y);
    v.z = h2pack(f0.z, f0.w);
    v.w = h2pack(f1.z, f1.w);
    *reinterpret_cast<uint4*>(g_wimg + (size_t)ci * CHUNKW + n * ROWW + qd * 4) = v;
}

// ---------------------------------------------------------------------------
// Fused kernel: 392 tile CTAs (full-K GEMM + inline WSL epilogue + ticket)
//               + 64 finisher CTAs (spin on ticket, per-b finish).
// 128 threads. Tile CTA: warp w -> ks = w>>1, m rows [(w&1)*16, +16).
// ---------------------------------------------------------------------------
__global__ void __launch_bounds__(128) wsl_fused_kernel(
    const float* __restrict__ x,
    const float* __restrict__ down_b,
    const float* __restrict__ fc_b,
    float* __restrict__ out,
    int B)
{
    extern __shared__ __align__(16) uint32_t smem[];
    const uint32_t sbase = smem_u32addr(smem);

    __shared__ float gm[32];
    __shared__ float xout_s[8];
    __shared__ float red2[8 * 4];
    __shared__ float psum[8];

    const int tid  = threadIdx.x;
    const int wid  = tid >> 5;
    const int lane = tid & 31;
    const int w4 = wid, lw = lane;   // alias for finisher section
    const int bx = blockIdx.x;

    if (bx < MTILES) {
        // ====================== tile CTA ======================
        const int g   = lane >> 2;
        const int c   = lane & 3;
        const int ksw = wid >> 1;           // 0: k 0..1023, 1: k 1024..2047
        const int wm  = (wid & 1) * 16;     // m-sub within tile
        const int tile = bx;
        const int m_base  = tile * M_TILE;
        const int ks_base = ksw * K_PER;
        const int ch0     = ksw * NCH_CTA;

        const int m0 = m_base + wm + g;
        const int m1 = m0 + 8;
        const int b0r = m0 / HW2, hw0 = m0 - b0r * HW2;
        const int b1r = m1 / HW2, hw1 = m1 - b1r * HW2;
        const float* pA0 = x + ((size_t)b0r * C_TOT) * HW2 + hw0;
        const float* pA1 = x + ((size_t)b1r * C_TOT) * HW2 + hw1;

        float acc[6][4];
#pragma unroll
        for (int t = 0; t < 6; t++)
#pragma unroll
            for (int j = 0; j < 4; j++) acc[t][j] = 0.f;

        float r0[2][8], r1[2][8];

        auto ldgA = [&](int sg, int p) {
            const int kb = ks_base + sg * 32 + 2 * c;
#pragma unroll
            for (int j = 0; j < 2; j++) {
                const size_t k = (size_t)(kb + 16 * j);
                r0[p][4 * j]     = __ldg(pA0 + k * HW2);
                r0[p][4 * j + 1] = __ldg(pA0 + (k + 1) * HW2);
                r0[p][4 * j + 2] = __ldg(pA0 + (k + 8) * HW2);
                r0[p][4 * j + 3] = __ldg(pA0 + (k + 9) * HW2);
                r1[p][4 * j]     = __ldg(pA1 + k * HW2);
                r1[p][4 * j + 1] = __ldg(pA1 + (k + 1) * HW2);
                r1[p][4 * j + 2] = __ldg(pA1 + (k + 8) * HW2);
                r1[p][4 * j + 3] = __ldg(pA1 + (k + 9) * HW2);
            }
        };

        // stage BOTH ks streams' chunk ch (2 x 13KB) into buffers
        //   stream s buffer parity p -> smem + (s*2+p)*CHUNKW
        auto issueB = [&](int ch) {
            const int par = ch & 1;
            const char* s0 = reinterpret_cast<const char*>(g_wimg + (size_t)ch * CHUNKW);
            const char* s1 = reinterpret_cast<const char*>(g_wimg + (size_t)(8 + ch) * CHUNKW);
            const uint32_t d0 = sbase + (uint32_t)(par * CHUNK_BYTES);
            const uint32_t d1 = sbase + (uint32_t)((2 + par) * CHUNK_BYTES);
            for (int u = tid; u < CP_UNITS; u += 128) {
                cp_async16(d0 + u * 16, s0 + u * 16);
                cp_async16(d1 + u * 16, s1 + u * 16);
            }
            asm volatile("cp.async.commit_group;" ::: "memory");
        };

        ldgA(0, 0);
        ldgA(1, 1);
        issueB(0);

        for (int ch = 0; ch < NCH_CTA; ch++) {
            if (ch + 1 < NCH_CTA) {
                issueB(ch + 1);
                asm volatile("cp.async.wait_group 1;" ::: "memory");
            } else {
                asm volatile("cp.async.wait_group 0;" ::: "memory");
            }
            __syncthreads();

            const uint32_t* buf = smem + (ksw * 2 + (ch & 1)) * CHUNKW;

#pragma unroll
            for (int kk = 0; kk < 4; kk++) {
                const int sg = ch * 4 + kk;
                const int p  = sg & 1;

                uint32_t af[2][4];
#pragma unroll
                for (int j = 0; j < 2; j++) {
                    af[j][0] = h2pack(r0[p][4 * j],     r0[p][4 * j + 1]);
                    af[j][1] = h2pack(r1[p][4 * j],     r1[p][4 * j + 1]);
                    af[j][2] = h2pack(r0[p][4 * j + 2], r0[p][4 * j + 3]);
                    af[j][3] = h2pack(r1[p][4 * j + 2], r1[p][4 * j + 3]);
                }

                if (sg + 2 < NSTEP) ldgA(sg + 2, p);

#pragma unroll
                for (int j = 0; j < 2; j++) {
                    const int s = kk * 2 + j;
#pragma unroll
                    for (int t = 0; t < 6; t++) {
                        const uint2 bw = *reinterpret_cast<const uint2*>(
                            buf + (t * 8 + g) * ROWW + s * 8 + 2 * c);
                        hmma16816(acc[t], af[j], bw.x, bw.y);
                    }
                }
            }
            __syncthreads();
        }

        // ---- combine ks halves in smem: ks0 stores (+bias), ks1 adds ----
        float* xs = reinterpret_cast<float*>(smem);   // [32][XST], 6.3 KB
        if (ksw == 0) {
#pragma unroll
            for (int t = 0; t < 6; t++) {
                const int n0 = t * 8 + 2 * c;
                const float bv0 = (n0 < 32) ? __ldg(down_b + n0) : 0.f;
                const float bv1 = (n0 + 1 < 32) ? __ldg(down_b + n0 + 1) : 0.f;
                xs[(wm + g) * XST + n0]         = acc[t][0] + bv0;
                xs[(wm + g) * XST + n0 + 1]     = acc[t][1] + bv1;
                xs[(wm + g + 8) * XST + n0]     = acc[t][2] + bv0;
                xs[(wm + g + 8) * XST + n0 + 1] = acc[t][3] + bv1;
            }
        }
        __syncthreads();
        if (ksw == 1) {
#pragma unroll
            for (int t = 0; t < 6; t++) {
                const int n0 = t * 8 + 2 * c;
                xs[(wm + g) * XST + n0]         += acc[t][0];
                xs[(wm + g) * XST + n0 + 1]     += acc[t][1];
                xs[(wm + g + 8) * XST + n0]     += acc[t][2];
                xs[(wm + g + 8) * XST + n0 + 1] += acc[t][3];
            }
        }
        __syncthreads();

        // ---- fused WSL epilogue (verified R8 mechanism, 32 rows) ----
        const int b_cta  = m_base / HW2;
        const int bsplit = min(M_TILE, (b_cta + 1) * HW2 - m_base);

        if (tid < 32) {
            const int map = tid;
            float mx0 = -INFINITY, mx1 = -INFINITY;
#pragma unroll 8
            for (int r = 0; r < M_TILE; r++) {
                float v = xs[r * XST + map];
                if (r < bsplit) mx0 = fmaxf(mx0, v); else mx1 = fmaxf(mx1, v);
            }
            atomicMax(&g_gmp_u[b_cta * 32 + map], fenc(mx0));
            if (bsplit < M_TILE)
                atomicMax(&g_gmp_u[(b_cta + 1) * 32 + map], fenc(mx1));
        } else if (tid < 64) {
            const int r = tid - 32;
            const int m = m_base + r;
            float cs[8], t2v[8];
#pragma unroll
            for (int j = 0; j < 8; j++) {
                cs[j] = xs[r * XST + 4 * j] + xs[r * XST + 4 * j + 1] +
                        xs[r * XST + 4 * j + 2] + xs[r * XST + 4 * j + 3];
                t2v[j] = xs[r * XST + 40 + j];
            }
            float4* cd = reinterpret_cast<float4*>(g_csum + (size_t)m * 8);
            cd[0] = make_float4(cs[0], cs[1], cs[2], cs[3]);
            cd[1] = make_float4(cs[4], cs[5], cs[6], cs[7]);
            float4* td = reinterpret_cast<float4*>(g_t2 + (size_t)m * 8);
            td[0] = make_float4(t2v[0], t2v[1], t2v[2], t2v[3]);
            td[1] = make_float4(t2v[4], t2v[5], t2v[6], t2v[7]);
        } else if (tid < 96) {
            const int idx  = tid - 64;       // 8 j x 4 parts of 8 rows
            const int j    = idx & 7;
            const int part = idx >> 3;
            float sa = 0.f, sb = 0.f;
#pragma unroll
            for (int rr = 0; rr < 8; rr++) {
                const int r = part * 8 + rr;
                float v = xs[r * XST + 32 + j];
                if (r < bsplit) sa += v; else sb += v;
            }
            if (part * 8 < bsplit)
                atomicAdd(&g_t1s[b_cta * 8 + j], sa);
            if (part * 8 + 7 >= bsplit)
                atomicAdd(&g_t1s[(b_cta + 1) * 8 + j], sb);
        }

        __threadfence();
        __syncthreads();
        if (tid == 0) {
            atomicAdd(&g_bdone[b_cta], 1);
            if (bsplit < M_TILE) atomicAdd(&g_bdone[b_cta + 1], 1);
        }
        return;
    }

    // ====================== finisher CTA ======================
    const int bb = bx - MTILES;
    if (bb >= B) return;

    if (tid == 0) {
        const int need = tiles_of_b(bb);
        while (((volatile int*)g_bdone)[bb] < need) __nanosleep(256);
    }
    __syncthreads();
    __threadfence();    // acquire

    if (tid < 32) gm[tid] = fdec(g_gmp_u[bb * 32 + tid]);
    __syncthreads();

    if (tid == 0) {
        float sc[8];
        float mx = -INFINITY;
        for (int j = 0; j < 8; j++) {
            sc[j] = 0.25f * (gm[4 * j] + gm[4 * j + 1] + gm[4 * j + 2] + gm[4 * j + 3]);
            mx = fmaxf(mx, sc[j]);
        }
        float se = 0.f;
        for (int j = 0; j < 8; j++) se += expf(sc[j] - mx);
        float lse = mx + logf(se);
        for (int j = 0; j < 8; j++) {
            float v = sc[j] - lse;
            xout_s[j] = v;
            out[(size_t)bb * 8 + j] = v;
        }
    }
    __syncthreads();

    float v[8];
#pragma unroll
    for (int j = 0; j < 8; j++) v[j] = 0.f;
    for (int h = tid; h < HW2; h += 128) {
        const size_t m = (size_t)bb * HW2 + h;
        const float4* cp = reinterpret_cast<const float4*>(g_csum + m * 8);
        float4 c0 = __ldg(cp), c1 = __ldg(cp + 1);
        float sal = xout_s[0] * c0.x + xout_s[1] * c0.y + xout_s[2] * c0.z +
                    xout_s[3] * c0.w + xout_s[4] * c1.x + xout_s[5] * c1.y +
                    xout_s[6] * c1.z + xout_s[7] * c1.w;
        sal *= (1.f / 32.f);
        const float4* tp = reinterpret_cast<const float4*>(g_t2 + m * 8);
        float4 t0 = __ldg(tp), t1 = __ldg(tp + 1);
        v[0] += sal * t0.x; v[1] += sal * t0.y; v[2] += sal * t0.z; v[3] += sal * t0.w;
        v[4] += sal * t1.x; v[5] += sal * t1.y; v[6] += sal * t1.z; v[7] += sal * t1.w;
    }
#pragma unroll
    for (int off = 16; off > 0; off >>= 1) {
#pragma unroll
        for (int j = 0; j < 8; j++)
            v[j] += __shfl_down_sync(0xffffffffu, v[j], off);
    }
    if (lw == 0) {
#pragma unroll
        for (int j = 0; j < 8; j++) red2[j * 4 + w4] = v[j];
    }
    __syncthreads();
    if (tid < 8) {
        psum[tid] = red2[tid * 4] + red2[tid * 4 + 1] +
                    red2[tid * 4 + 2] + red2[tid * 4 + 3];
    }
    __syncthreads();

    if (tid == 0) {
        float lg[8];
        float mx = -INFINITY;
        for (int j = 0; j < 8; j++) {
            lg[j] = (g_t1s[bb * 8 + j] + psum[j]) * (1.f / 196.f) + fc_b[j];
            mx = fmaxf(mx, lg[j]);
        }
        float se = 0.f;
        for (int j = 0; j < 8; j++) se += expf(lg[j] - mx);
        float lse = mx + logf(se);
        for (int j = 0; j < 8; j++)
            out[(size_t)B * 8 + (size_t)bb * 8 + j] = lg[j] - lse;
    }
}

// ---------------------------------------------------------------------------
extern "C" void kernel_launch(void* const* d_in, const int* in_sizes, int n_in,
                              void* d_out, int out_size)
{
    const float* x      = (const float*)d_in[0];
    const float* down_w = (const float*)d_in[1];
    const float* down_b = (const float*)d_in[2];
    const float* fc_w   = (const float*)d_in[3];
    const float* fc_b   = (const float*)d_in[4];
    float* out = (float*)d_out;

    int B = in_sizes[0] / (C_TOT * HW2);   // 64

    static bool attr_set = false;
    if (!attr_set) {
        cudaFuncSetAttribute(wsl_fused_kernel,
                             cudaFuncAttributeMaxDynamicSharedMemorySize, SMEM_BYTES);
        attr_set = true;
    }

    wsl_prep_kernel<<<48, 256>>>(down_w, fc_w);
    wsl_fused_kernel<<<MTILES + MAXB, 128, SMEM_BYTES>>>(x, down_b, fc_b, out, B);
}

// round 14
// speedup vs baseline: 1.5381x; 1.5381x over previous
#include <cuda_runtime.h>
#include <cuda_fp16.h>
#include <cstdint>
#include <math.h>

// ---------------------------------------------------------------------------
// Problem constants
// ---------------------------------------------------------------------------
#define C_TOT   2048
#define HW2     196
#define O_REAL  48
#define MAXB    64
#define M_TILE  64
#define MTILES  196            // 12544 / 64
#define KSPLIT  2
#define K_PER   (C_TOT / KSPLIT)   // 1024
#define KC      128
#define NCH_CTA (K_PER / KC)   // 8 chunks per CTA
#define NCH_ALL (C_TOT / KC)   // 16 chunks total
#define NSTEP   (K_PER / 32)   // 32 k32 steps per CTA

// W fp16 image: per chunk, 48 rows x 68 words (64 data + 4 pad)
#define ROWW    68
#define CHUNKW  (48 * ROWW)            // 3264 words
#define CHUNK_BYTES (CHUNKW * 4)       // 13056
#define CP_UNITS (CHUNK_BYTES / 16)    // 816

#define XST     52                     // epilogue smem row stride (words)

// Scratch
__device__ uint32_t g_wimg[(size_t)NCH_ALL * CHUNKW];                   // 209 KB
__device__ float    g_part[(size_t)KSPLIT * MTILES * M_TILE * O_REAL]; // 4.8 MB
__device__ float    g_M[(size_t)MAXB * 64];                  // [b][j*8+i] accum
__device__ float    g_t1s[(size_t)MAXB * 8];                 // atomicAdd acc
__device__ unsigned g_gmp_u[(size_t)MAXB * 32];              // atomicMax acc

// ---------------------------------------------------------------------------
// helpers
// ---------------------------------------------------------------------------
__device__ __forceinline__ void hmma16816(float* c, const uint32_t* a,
                                          uint32_t b0, uint32_t b1) {
    asm volatile(
        "mma.sync.aligned.m16n8k16.row.col.f32.f16.f16.f32 "
        "{%0,%1,%2,%3}, {%4,%5,%6,%7}, {%8,%9}, {%0,%1,%2,%3};"
        : "+f"(c[0]), "+f"(c[1]), "+f"(c[2]), "+f"(c[3])
        : "r"(a[0]), "r"(a[1]), "r"(a[2]), "r"(a[3]), "r"(b0), "r"(b1));
}
__device__ __forceinline__ uint32_t h2pack(float e, float o) {
    uint32_t r;
    asm("cvt.rn.f16x2.f32 %0, %1, %2;" : "=r"(r) : "f"(o), "f"(e));
    return r;
}
__device__ __forceinline__ void cp_async16(uint32_t saddr, const void* gaddr) {
    asm volatile("cp.async.cg.shared.global [%0], [%1], 16;" :: "r"(saddr), "l"(gaddr));
}
__device__ __forceinline__ uint32_t smem_u32addr(const void* p) {
    uint32_t a;
    asm("{ .reg .u64 t; cvta.to.shared.u64 t, %1; cvt.u32.u64 %0, t; }" : "=r"(a) : "l"(p));
    return a;
}
// order-preserving float<->uint for atomicMax
__device__ __forceinline__ unsigned fenc(float f) {
    unsigned u = __float_as_uint(f);
    return (u & 0x80000000u) ? ~u : (u | 0x80000000u);
}
__device__ __forceinline__ float fdec(unsigned u) {
    return __uint_as_float((u & 0x80000000u) ? (u & 0x7FFFFFFFu) : ~u);
}

// ---------------------------------------------------------------------------
// Prep: W -> fp16 image (4 words/thread) + zero accumulators.
// ---------------------------------------------------------------------------
__global__ void __launch_bounds__(256) wsl_prep_kernel(
    const float* __restrict__ down_w,
    const float* __restrict__ fc_w)
{
    int q = blockIdx.x * 256 + threadIdx.x;

    if (q < MAXB * 32) g_gmp_u[q] = 0u;
    if (q < MAXB * 8)  g_t1s[q] = 0.f;
    if (q < MAXB * 64) g_M[q] = 0.f;

    if (q >= NCH_ALL * 48 * 16) return;
    int ci  = q / 768;
    int rem = q - ci * 768;
    int n   = rem >> 4;
    int qd  = rem & 15;
    int s   = qd >> 1;
    int bk  = s * 16 + 4 * (qd & 1);

    const float* wr;
    if (n < 32)      wr = down_w + (size_t)n * C_TOT;
    else if (n < 40) wr = fc_w + (size_t)(n - 32) * (2 * C_TOT);
    else             wr = fc_w + (size_t)(n - 40) * (2 * C_TOT) + C_TOT;

    const float* src = wr + ci * KC + bk;
    float4 f0 = *reinterpret_cast<const float4*>(src);
    float4 f1 = *reinterpret_cast<const float4*>(src + 8);

    uint4 v;
    v.x = h2pack(f0.x, f0.y);
    v.y = h2pack(f1.x, f1.y);
    v.z = h2pack(f0.z, f0.w);
    v.w = h2pack(f1.z, f1.w);
    *reinterpret_cast<uint4*>(g_wimg + (size_t)ci * CHUNKW + n * ROWW + qd * 4) = v;
}

// ---------------------------------------------------------------------------
// Kernel A: fp16 GEMM (best-known R7/R10 config), coalesced partial write.
// Grid (196, 2), 128 threads. Warp w: m rows [w*16, w*16+16), all 48 n.
// ---------------------------------------------------------------------------
__global__ void __launch_bounds__(128) wsl_mma_kernel(const float* __restrict__ x)
{
    __shared__ __align__(16) uint32_t smem[2 * CHUNKW];   // 26.1 KB
    const uint32_t sbase = smem_u32addr(smem);

    const int tid  = threadIdx.x;
    const int wid  = tid >> 5;
    const int lane = tid & 31;
    const int g    = lane >> 2;
    const int c    = lane & 3;
    const int mw   = wid * 16;
    const int tile = blockIdx.x;
    const int ks   = blockIdx.y;
    const int m_base  = tile * M_TILE;
    const int ks_base = ks * K_PER;
    const int ch0     = ks * NCH_CTA;

    const int m0 = m_base + mw + g;
    const int m1 = m0 + 8;
    const int b0r = m0 / HW2, hw0 = m0 - b0r * HW2;
    const int b1r = m1 / HW2, hw1 = m1 - b1r * HW2;
    const float* pA0 = x + ((size_t)b0r * C_TOT) * HW2 + hw0;
    const float* pA1 = x + ((size_t)b1r * C_TOT) * HW2 + hw1;

    float acc[6][4];
#pragma unroll
    for (int t = 0; t < 6; t++)
#pragma unroll
        for (int j = 0; j < 4; j++) acc[t][j] = 0.f;

    float r0[2][8], r1[2][8];

    auto ldgA = [&](int sg, int p) {
        const int kb = ks_base + sg * 32 + 2 * c;
#pragma unroll
        for (int j = 0; j < 2; j++) {
            const size_t k = (size_t)(kb + 16 * j);
            r0[p][4 * j]     = __ldg(pA0 + k * HW2);
            r0[p][4 * j + 1] = __ldg(pA0 + (k + 1) * HW2);
            r0[p][4 * j + 2] = __ldg(pA0 + (k + 8) * HW2);
            r0[p][4 * j + 3] = __ldg(pA0 + (k + 9) * HW2);
            r1[p][4 * j]     = __ldg(pA1 + k * HW2);
            r1[p][4 * j + 1] = __ldg(pA1 + (k + 1) * HW2);
            r1[p][4 * j + 2] = __ldg(pA1 + (k + 8) * HW2);
            r1[p][4 * j + 3] = __ldg(pA1 + (k + 9) * HW2);
        }
    };

    auto issueB = [&](int ch) {
        const char* src = reinterpret_cast<const char*>(g_wimg + (size_t)(ch0 + ch) * CHUNKW);
        const uint32_t dst = sbase + (uint32_t)((ch & 1) * CHUNK_BYTES);
        for (int u = tid; u < CP_UNITS; u += 128)
            cp_async16(dst + u * 16, src + u * 16);
        asm volatile("cp.async.commit_group;" ::: "memory");
    };

    ldgA(0, 0);
    ldgA(1, 1);
    issueB(0);

    for (int ch = 0; ch < NCH_CTA; ch++) {
        if (ch + 1 < NCH_CTA) {
            issueB(ch + 1);
            asm volatile("cp.async.wait_group 1;" ::: "memory");
        } else {
            asm volatile("cp.async.wait_group 0;" ::: "memory");
        }
        __syncthreads();

        const uint32_t* buf = smem + (ch & 1) * CHUNKW;

#pragma unroll
        for (int kk = 0; kk < 4; kk++) {
            const int sg = ch * 4 + kk;
            const int p  = sg & 1;

            uint32_t af[2][4];
#pragma unroll
            for (int j = 0; j < 2; j++) {
                af[j][0] = h2pack(r0[p][4 * j],     r0[p][4 * j + 1]);
                af[j][1] = h2pack(r1[p][4 * j],     r1[p][4 * j + 1]);
                af[j][2] = h2pack(r0[p][4 * j + 2], r0[p][4 * j + 3]);
                af[j][3] = h2pack(r1[p][4 * j + 2], r1[p][4 * j + 3]);
            }

            if (sg + 2 < NSTEP) ldgA(sg + 2, p);

#pragma unroll
            for (int j = 0; j < 2; j++) {
                const int s = kk * 2 + j;
#pragma unroll
                for (int t = 0; t < 6; t++) {
                    const uint2 bw = *reinterpret_cast<const uint2*>(
                        buf + (t * 8 + g) * ROWW + s * 8 + 2 * c);
                    hmma16816(acc[t], af[j], bw.x, bw.y);
                }
            }
        }
        __syncthreads();
    }

    // ---- stash acc into smem xs[64][XST], then coalesced partial write ----
    float* xs = reinterpret_cast<float*>(smem);
#pragma unroll
    for (int t = 0; t < 6; t++) {
        const int n0 = t * 8 + 2 * c;
        xs[(mw + g) * XST + n0]         = acc[t][0];
        xs[(mw + g) * XST + n0 + 1]     = acc[t][1];
        xs[(mw + g + 8) * XST + n0]     = acc[t][2];
        xs[(mw + g + 8) * XST + n0 + 1] = acc[t][3];
    }
    __syncthreads();

    {
        float4* dst = reinterpret_cast<float4*>(
            g_part + ((size_t)ks * MTILES + tile) * (M_TILE * O_REAL));
#pragma unroll
        for (int i = 0; i < 6; i++) {
            const int fi = tid + i * 128;           // 768 float4s
            const int r  = (fi * 4) / O_REAL;
            const int cc = (fi * 4) % O_REAL;
            dst[fi] = *reinterpret_cast<const float4*>(xs + r * XST + cc);
        }
    }
}

// ---------------------------------------------------------------------------
// Kernel B1: per-tile combine + fused reductions (gmp, t1, M-matrix).
// Grid 196, 128 threads. Partials are L2-hot.
// ---------------------------------------------------------------------------
__global__ void __launch_bounds__(128) wsl_b1_kernel(const float* __restrict__ down_b)
{
    __shared__ __align__(16) float xs[M_TILE * XST];   // 13.3 KB
    __shared__ float cls_s[M_TILE * 9];                // 2.3 KB (stride 9)

    const int tid  = threadIdx.x;
    const int tile = blockIdx.x;
    const int m_base = tile * M_TILE;

    // combine both K-split partials (+ bias)
    {
        const float4* p0 = reinterpret_cast<const float4*>(
            g_part + (size_t)tile * (M_TILE * O_REAL));
        const float4* p1 = reinterpret_cast<const float4*>(
            g_part + ((size_t)MTILES + tile) * (M_TILE * O_REAL));
#pragma unroll
        for (int i = 0; i < 6; i++) {
            const int fi = tid + i * 128;
            const int r  = (fi * 4) / O_REAL;
            const int cc = (fi * 4) % O_REAL;
            float4 a = __ldg(p0 + fi);
            float4 b = __ldg(p1 + fi);
            float4 v = make_float4(a.x + b.x, a.y + b.y, a.z + b.z, a.w + b.w);
            if (cc < 32) {
                v.x += __ldg(down_b + cc);
                v.y += __ldg(down_b + cc + 1);
                v.z += __ldg(down_b + cc + 2);
                v.w += __ldg(down_b + cc + 3);
            }
            *reinterpret_cast<float4*>(xs + r * XST + cc) = v;
        }
    }
    __syncthreads();

    const int b_cta  = m_base / HW2;
    const int bsplit = min(M_TILE, (b_cta + 1) * HW2 - m_base);

    // Phase 2
    if (tid < 32) {
        // GMP per map
        const int map = tid;
        float mx0 = -INFINITY, mx1 = -INFINITY;
#pragma unroll 8
        for (int r = 0; r < M_TILE; r++) {
            float v = xs[r * XST + map];
            if (r < bsplit) mx0 = fmaxf(mx0, v); else mx1 = fmaxf(mx1, v);
        }
        atomicMax(&g_gmp_u[b_cta * 32 + map], fenc(mx0));
        if (bsplit < M_TILE)
            atomicMax(&g_gmp_u[(b_cta + 1) * 32 + map], fenc(mx1));
    } else if (tid < 96) {
        // per-row class sums -> cls_s
        const int r = tid - 32;
#pragma unroll
        for (int j = 0; j < 8; j++) {
            cls_s[r * 9 + j] = xs[r * XST + 4 * j] + xs[r * XST + 4 * j + 1] +
                               xs[r * XST + 4 * j + 2] + xs[r * XST + 4 * j + 3];
        }
    } else {
        // t1 row sums -> atomicAdd partials
        const int idx  = tid - 96;       // 8 j x 4 parts
        const int j    = idx & 7;
        const int part = idx >> 3;       // 4 parts x 16 rows
        float sa = 0.f, sb = 0.f;
#pragma unroll
        for (int rr = 0; rr < 16; rr++) {
            const int r = part * 16 + rr;
            float v = xs[r * XST + 32 + j];
            if (r < bsplit) sa += v; else sb += v;
        }
        if (part * 16 < bsplit)
            atomicAdd(&g_t1s[b_cta * 8 + j], sa);
        if (part * 16 + 15 >= bsplit)
            atomicAdd(&g_t1s[(b_cta + 1) * 8 + j], sb);
    }
    __syncthreads();

    // Phase 3: M[j][i] = sum_r cls[r][j] * t2[r][i]  (threads 32..95)
    if (tid >= 32 && tid < 96) {
        const int idx = tid - 32;
        const int j = idx >> 3;
        const int i = idx & 7;
        float sa = 0.f, sb = 0.f;
#pragma unroll 8
        for (int r = 0; r < M_TILE; r++) {
            float p = cls_s[r * 9 + j] * xs[r * XST + 40 + i];
            if (r < bsplit) sa += p; else sb += p;
        }
        atomicAdd(&g_M[b_cta * 64 + j * 8 + i], sa);
        if (bsplit < M_TILE)
            atomicAdd(&g_M[(b_cta + 1) * 64 + j * 8 + i], sb);
    }
}

// ---------------------------------------------------------------------------
// Kernel B2: tiny finisher. Grid 64, 64 threads. Reads ~1.3KB per CTA.
// ---------------------------------------------------------------------------
__global__ void __launch_bounds__(64) wsl_b2_kernel(
    const float* __restrict__ fc_b,
    float* __restrict__ out,
    int B)
{
    __shared__ float gm[32];
    __shared__ float xout[8];
    __shared__ float lg_s[8];

    const int b = blockIdx.x;
    const int tid = threadIdx.x;

    if (tid < 32) gm[tid] = fdec(g_gmp_u[b * 32 + tid]);
    __syncthreads();

    if (tid == 0) {
        float sc[8];
        float mx = -INFINITY;
        for (int j = 0; j < 8; j++) {
            sc[j] = 0.25f * (gm[4 * j] + gm[4 * j + 1] + gm[4 * j + 2] + gm[4 * j + 3]);
            mx = fmaxf(mx, sc[j]);
        }
        float se = 0.f;
        for (int j = 0; j < 8; j++) se += expf(sc[j] - mx);
        float lse = mx + logf(se);
        for (int j = 0; j < 8; j++) {
            float v = sc[j] - lse;
            xout[j] = v;
            out[(size_t)b * 8 + j] = v;
        }
    }
    __syncthreads();

    if (tid < 8) {
        const int i = tid;
        float s = 0.f;
#pragma unroll
        for (int j = 0; j < 8; j++)
            s += xout[j] * g_M[b * 64 + j * 8 + i];
        lg_s[i] = (g_t1s[b * 8 + i] + s * (1.f / 32.f)) * (1.f / 196.f) + __ldg(fc_b + i);
    }
    __syncthreads();

    if (tid == 0) {
        float mx = -INFINITY;
        for (int j = 0; j < 8; j++) mx = fmaxf(mx, lg_s[j]);
        float se = 0.f;
        for (int j = 0; j < 8; j++) se += expf(lg_s[j] - mx);
        float lse = mx + logf(se);
        for (int j = 0; j < 8; j++)
            out[(size_t)B * 8 + (size_t)b * 8 + j] = lg_s[j] - lse;
    }
}

// ---------------------------------------------------------------------------
extern "C" void kernel_launch(void* const* d_in, const int* in_sizes, int n_in,
                              void* d_out, int out_size)
{
    const float* x      = (const float*)d_in[0];
    const float* down_w = (const float*)d_in[1];
    const float* down_b = (const float*)d_in[2];
    const float* fc_w   = (const float*)d_in[3];
    const float* fc_b   = (const float*)d_in[4];
    float* out = (float*)d_out;

    int B = in_sizes[0] / (C_TOT * HW2);   // 64

    wsl_prep_kernel<<<48, 256>>>(down_w, fc_w);
    dim3 gridA(MTILES, KSPLIT);
    wsl_mma_kernel<<<gridA, 128>>>(x);
    wsl_b1_kernel<<<MTILES, 128>>>(down_b);
    wsl_b2_kernel<<<B, 64>>>(fc_b, out, B);
}